// round 1
// baseline (speedup 1.0000x reference)
#include <cuda_runtime.h>
#include <math.h>

#define BB   16
#define NN   96
#define HH   256
#define BINC 11

// Scratch for y = x @ W_atom  (B*N*H floats = 1.5 MB). __device__ global: no allocation.
__device__ float g_y[BB * NN * HH];

// ---------------------------------------------------------------------------
// Kernel 1: y[b,n,k] = sum_h x[b,n,h] * W_atom[h,k]
// 1536 blocks (one per row), 256 threads (one per k).
// W_atom is 256 KB, reused by all blocks -> L2 resident after first wave.
// ---------------------------------------------------------------------------
__global__ __launch_bounds__(256) void proj_kernel(const float* __restrict__ x,
                                                   const float* __restrict__ W_atom) {
    const int row = blockIdx.x;       // b*NN + n
    const int k   = threadIdx.x;
    __shared__ float xs[HH];
    xs[k] = x[row * HH + k];
    __syncthreads();
    float acc = 0.f;
#pragma unroll 8
    for (int h = 0; h < HH; ++h)
        acc = fmaf(xs[h], __ldg(&W_atom[h * HH + k]), acc);
    g_y[row * HH + k] = acc;
}

// ---------------------------------------------------------------------------
// Kernel 2: fused pair loop + score + context.
// One block per (b,i). 8 warps; warp w handles j = w, w+8, ...
// Per (j): hidden_k = relu(y_i[k] + y_j[k] + bin(b,i,j,:) @ W_bin[:,k] + b_bin[k])
//          s = sigmoid(hidden . w_score + b_score)       (warp-shuffle reduce)
//          pair_out[b,i,j,k] = x_i[k] + x_j[k]           (coalesced 128B stores)
// Epilogue: context[b,i,k] = sum_j att[j] * x[b,j,k]
// ---------------------------------------------------------------------------
__global__ __launch_bounds__(256) void pair_kernel(
    const float* __restrict__ x,
    const float* __restrict__ bin,
    const float* __restrict__ W_bin,
    const float* __restrict__ b_bin,
    const float* __restrict__ w_score,
    const float* __restrict__ b_score,
    float* __restrict__ ctx_out,
    float* __restrict__ pair_out)
{
    const int bi   = blockIdx.x;      // b*NN + i
    const int b    = bi / NN;
    const int tid  = threadIdx.x;
    const int warp = tid >> 5;
    const int lane = tid & 31;

    __shared__ float Wb_s[BINC * HH];  // 11 KB
    __shared__ float bb_s[HH];
    __shared__ float ws_s[HH];
    __shared__ float yi_s[HH];
    __shared__ float xi_s[HH];
    __shared__ float att_s[NN];

    for (int idx = tid; idx < BINC * HH; idx += 256) Wb_s[idx] = W_bin[idx];
    bb_s[tid] = b_bin[tid];
    ws_s[tid] = w_score[tid];
    yi_s[tid] = g_y[bi * HH + tid];
    xi_s[tid] = x[bi * HH + tid];
    __syncthreads();

    const float bscore = __ldg(b_score);

    for (int j = warp; j < NN; j += 8) {
        const float* binp = bin + ((size_t)bi * NN + j) * BINC;
        float bc[BINC];
#pragma unroll
        for (int c = 0; c < BINC; ++c) bc[c] = __ldg(&binp[c]);   // warp-broadcast

        const float* yj = g_y + (b * NN + j) * HH;   // L2-resident
        const float* xj = x   + (b * NN + j) * HH;   // L2-resident
        float* po = pair_out + (((size_t)bi * NN) + j) * HH;

        float s = 0.f;
#pragma unroll
        for (int t = 0; t < 8; ++t) {
            const int k = lane + 32 * t;             // coalesced across the warp
            float acc = bb_s[k];
#pragma unroll
            for (int c = 0; c < BINC; ++c)
                acc = fmaf(bc[c], Wb_s[c * HH + k], acc);
            acc += yi_s[k] + yj[k];
            acc = fmaxf(acc, 0.f);
            s = fmaf(acc, ws_s[k], s);
            po[k] = xi_s[k] + xj[k];                 // atom_pair output
        }
        // warp reduction of the score dot-product
#pragma unroll
        for (int off = 16; off > 0; off >>= 1)
            s += __shfl_xor_sync(0xffffffffu, s, off);
        if (lane == 0)
            att_s[j] = 1.f / (1.f + __expf(-(s + bscore)));
    }
    __syncthreads();

    // context[b,i,tid] = sum_j att[j] * x[b,j,tid]
    const float* xb = x + b * NN * HH;
    float acc = 0.f;
#pragma unroll 4
    for (int j = 0; j < NN; ++j)
        acc = fmaf(att_s[j], xb[j * HH + tid], acc);
    ctx_out[bi * HH + tid] = acc;
}

// ---------------------------------------------------------------------------
extern "C" void kernel_launch(void* const* d_in, const int* in_sizes, int n_in,
                              void* d_out, int out_size) {
    const float* x       = (const float*)d_in[0];  // (B,N,H)
    const float* bin     = (const float*)d_in[1];  // (B,N,N,BIN)
    const float* W_atom  = (const float*)d_in[2];  // (H,H)
    const float* W_bin   = (const float*)d_in[3];  // (BIN,H)
    const float* b_bin   = (const float*)d_in[4];  // (H,)
    const float* w_score = (const float*)d_in[5];  // (H,1)
    const float* b_score = (const float*)d_in[6];  // (1,)

    float* out  = (float*)d_out;
    float* ctx  = out;                                  // context: B*N*H
    float* pair = out + (size_t)BB * NN * HH;           // atom_pair: B*N*N*H

    proj_kernel<<<BB * NN, 256>>>(x, W_atom);
    pair_kernel<<<BB * NN, 256>>>(x, bin, W_bin, b_bin, w_score, b_score, ctx, pair);
}

// round 3
// speedup vs baseline: 1.4118x; 1.4118x over previous
#include <cuda_runtime.h>
#include <math.h>

#define BB   16
#define NN   96
#define HH   256
#define BINC 11
#define IT   4      // i-rows per block (pair kernel)

// Scratch for y = x @ W_atom  (1.5 MB) — __device__ global, no allocation.
__device__ float g_y[BB * NN * HH];

// ---- packed f32x2 helpers (carrier: u64 .b64 regs, "l" constraint) --------
typedef unsigned long long f2;
__device__ __forceinline__ f2 pk(float lo, float hi) {
    f2 r; asm("mov.b64 %0, {%1,%2};" : "=l"(r) : "f"(lo), "f"(hi)); return r;
}
__device__ __forceinline__ void upk(f2 v, float& lo, float& hi) {
    asm("mov.b64 {%0,%1}, %2;" : "=f"(lo), "=f"(hi) : "l"(v));
}
__device__ __forceinline__ f2 fma2(f2 a, f2 b, f2 c) {
    f2 d; asm("fma.rn.f32x2 %0, %1, %2, %3;" : "=l"(d) : "l"(a), "l"(b), "l"(c)); return d;
}
__device__ __forceinline__ f2 add2(f2 a, f2 b) {
    f2 d; asm("add.rn.f32x2 %0, %1, %2;" : "=l"(d) : "l"(a), "l"(b)); return d;
}

// ---------------------------------------------------------------------------
// Kernel 1: y = x @ W_atom, tiled: 16 rows per block share the W_atom stream.
// L2 traffic for W_atom: 96 blocks * 256KB = 25 MB (was 393 MB).
// ---------------------------------------------------------------------------
__global__ __launch_bounds__(256) void proj_kernel(const float* __restrict__ x,
                                                   const float* __restrict__ W) {
    __shared__ float xs[16 * HH];
    const int r0  = blockIdx.x * 16;
    const int tid = threadIdx.x;
    for (int idx = tid; idx < 16 * HH; idx += 256) xs[idx] = x[r0 * HH + idx];
    __syncthreads();

    const int k = tid;
    f2 acc[16];
#pragma unroll
    for (int r = 0; r < 16; ++r) acc[r] = 0ull;

    const ulonglong2* xs2 = (const ulonglong2*)xs;   // [r*64 + h4] = 4 h values
#pragma unroll 4
    for (int h4 = 0; h4 < 64; ++h4) {
        const int h = h4 * 4;
        float w0 = __ldg(&W[(h + 0) * HH + k]);
        float w1 = __ldg(&W[(h + 1) * HH + k]);
        float w2 = __ldg(&W[(h + 2) * HH + k]);
        float w3 = __ldg(&W[(h + 3) * HH + k]);
        f2 wa = pk(w0, w1), wb = pk(w2, w3);
#pragma unroll
        for (int r = 0; r < 16; ++r) {
            ulonglong2 xv = xs2[r * 64 + h4];
            acc[r] = fma2(xv.x, wa, acc[r]);
            acc[r] = fma2(xv.y, wb, acc[r]);
        }
    }
#pragma unroll
    for (int r = 0; r < 16; ++r) {
        float lo, hi; upk(acc[r], lo, hi);
        g_y[(r0 + r) * HH + k] = lo + hi;
    }
}

// ---------------------------------------------------------------------------
// Kernel 2: fused pair + score + context.
// Block = (b, 4 consecutive i). 8 warps: warp w -> i = i0 + (w&3), j-phase w>>2.
// Each warp owns the full H=256 per j (8 k per thread, quads at 128*tt+4*lane).
// W_bin / w_score / base / x_i / ctx all in REGISTERS (no hot-loop LDS).
// Context fused: att known to all lanes after warp reduce.
// ---------------------------------------------------------------------------
__global__ __launch_bounds__(256, 1) void pair_kernel(
    const float* __restrict__ x,
    const float* __restrict__ bin,
    const float* __restrict__ W_bin,
    const float* __restrict__ b_bin,
    const float* __restrict__ w_score,
    const float* __restrict__ b_score,
    float* __restrict__ ctx_out,
    float* __restrict__ pair_out)
{
    const int blk = blockIdx.x;             // 0 .. B*NN/IT-1
    const int b   = blk / (NN / IT);
    const int i0  = (blk % (NN / IT)) * IT;
    const int tid = threadIdx.x;
    const int w   = tid >> 5;
    const int L   = tid & 31;
    const int i   = i0 + (w & 3);
    const int jph = w >> 2;                 // 0 or 1; j = jph + 2t
    const int bi  = b * NN + i;

    __shared__ f2 cps[8][128];              // per-warp ctx partials (f32x2 pairs)

    // ---- register-resident parameters for this thread's k-slice ----
    f2 wb[BINC][4];
#pragma unroll
    for (int c = 0; c < BINC; ++c) {
        const ulonglong2* p = (const ulonglong2*)(W_bin + c * HH);
        ulonglong2 a = p[L], bq = p[32 + L];
        wb[c][0] = a.x; wb[c][1] = a.y; wb[c][2] = bq.x; wb[c][3] = bq.y;
    }
    f2 ws[4];
    {
        const ulonglong2* p = (const ulonglong2*)w_score;
        ulonglong2 a = p[L], bq = p[32 + L];
        ws[0] = a.x; ws[1] = a.y; ws[2] = bq.x; ws[3] = bq.y;
    }
    f2 base[4], xi[4];
    {
        const ulonglong2* yp = (const ulonglong2*)(g_y + bi * HH);
        const ulonglong2* bp = (const ulonglong2*)b_bin;
        const ulonglong2* xp = (const ulonglong2*)(x + bi * HH);
        ulonglong2 y0 = yp[L], y1 = yp[32 + L];
        ulonglong2 b0 = bp[L], b1 = bp[32 + L];
        ulonglong2 x0 = xp[L], x1 = xp[32 + L];
        base[0] = add2(y0.x, b0.x); base[1] = add2(y0.y, b0.y);
        base[2] = add2(y1.x, b1.x); base[3] = add2(y1.y, b1.y);
        xi[0] = x0.x; xi[1] = x0.y; xi[2] = x1.x; xi[3] = x1.y;
    }
    f2 ctx[4] = {0ull, 0ull, 0ull, 0ull};

    const ulonglong2* ybase = (const ulonglong2*)(g_y + b * NN * HH);
    const ulonglong2* xbase = (const ulonglong2*)(x   + b * NN * HH);
    const float*      binb  = bin + (size_t)bi * NN * BINC;
    ulonglong2*       pob   = (ulonglong2*)(pair_out + (size_t)bi * NN * HH);
    const float       bsc   = __ldg(b_score);

    // ---- software-pipelined j loop ----
    int j = jph;
    ulonglong2 ya = ybase[j * 64 + L],      yb = ybase[j * 64 + 32 + L];
    ulonglong2 xa = xbase[j * 64 + L],      xb = xbase[j * 64 + 32 + L];
    float bc[BINC];
#pragma unroll
    for (int c = 0; c < BINC; ++c) bc[c] = __ldg(binb + j * BINC + c);

    for (int t = 0; t < NN / 2; ++t) {
        // hidden init & pair sums (consume y/x buffers)
        f2 h0 = add2(base[0], ya.x), h1 = add2(base[1], ya.y);
        f2 h2 = add2(base[2], yb.x), h3 = add2(base[3], yb.y);
        f2 p0 = add2(xi[0], xa.x),  p1 = add2(xi[1], xa.y);
        f2 p2 = add2(xi[2], xb.x),  p3 = add2(xi[3], xb.y);
        f2 cx0 = xa.x, cx1 = xa.y, cx2 = xb.x, cx3 = xb.y;  // saved x_j for ctx

        // prefetch next j's y/x (buffers dead now)
        int jn = j + 2; if (jn >= NN) jn = j;
        ya = ybase[jn * 64 + L]; yb = ybase[jn * 64 + 32 + L];
        xa = xbase[jn * 64 + L]; xb = xbase[jn * 64 + 32 + L];

        // bin projection: 44 packed FMAs from registers
#pragma unroll
        for (int c = 0; c < BINC; ++c) {
            f2 bc2 = pk(bc[c], bc[c]);
            h0 = fma2(bc2, wb[c][0], h0);
            h1 = fma2(bc2, wb[c][1], h1);
            h2 = fma2(bc2, wb[c][2], h2);
            h3 = fma2(bc2, wb[c][3], h3);
        }
        // prefetch next bin coeffs (bc dead)
#pragma unroll
        for (int c = 0; c < BINC; ++c) bc[c] = __ldg(binb + jn * BINC + c);

        // relu + score dot
        float f0, f1, f2v, f3, f4, f5, f6, f7;
        upk(h0, f0, f1); upk(h1, f2v, f3); upk(h2, f4, f5); upk(h3, f6, f7);
        f0 = fmaxf(f0, 0.f); f1 = fmaxf(f1, 0.f); f2v = fmaxf(f2v, 0.f); f3 = fmaxf(f3, 0.f);
        f4 = fmaxf(f4, 0.f); f5 = fmaxf(f5, 0.f); f6 = fmaxf(f6, 0.f); f7 = fmaxf(f7, 0.f);
        f2 r0 = pk(f0, f1), r1 = pk(f2v, f3), r2 = pk(f4, f5), r3 = pk(f6, f7);
        f2 sp = fma2(r0, ws[0], fma2(r1, ws[1], fma2(r2, ws[2], fma2(r3, ws[3], 0ull))));
        float slo, shi; upk(sp, slo, shi);
        float s = slo + shi;
#pragma unroll
        for (int off = 16; off > 0; off >>= 1)
            s += __shfl_xor_sync(0xffffffffu, s, off);

        const float att = 1.f / (1.f + __expf(-(s + bsc)));
        const f2 att2 = pk(att, att);
        ctx[0] = fma2(att2, cx0, ctx[0]);
        ctx[1] = fma2(att2, cx1, ctx[1]);
        ctx[2] = fma2(att2, cx2, ctx[2]);
        ctx[3] = fma2(att2, cx3, ctx[3]);

        // atom_pair output: 2x 128-bit coalesced stores
        pob[j * 64 + L]      = make_ulonglong2(p0, p1);
        pob[j * 64 + 32 + L] = make_ulonglong2(p2, p3);

        j += 2;
    }

    // ---- cross-warp context reduction (warps {i, i+4} share an i) ----
    cps[w][2 * L + 0]      = ctx[0];
    cps[w][2 * L + 1]      = ctx[1];
    cps[w][64 + 2 * L + 0] = ctx[2];
    cps[w][64 + 2 * L + 1] = ctx[3];
    __syncthreads();

    for (int d = tid; d < IT * 128; d += 256) {
        const int ii = d >> 7, dd = d & 127;
        f2 v = add2(cps[ii][dd], cps[ii + 4][dd]);
        ((f2*)ctx_out)[(size_t)(b * NN + i0 + ii) * 128 + dd] = v;
    }
}

// ---------------------------------------------------------------------------
extern "C" void kernel_launch(void* const* d_in, const int* in_sizes, int n_in,
                              void* d_out, int out_size) {
    const float* x       = (const float*)d_in[0];
    const float* bin     = (const float*)d_in[1];
    const float* W_atom  = (const float*)d_in[2];
    const float* W_bin   = (const float*)d_in[3];
    const float* b_bin   = (const float*)d_in[4];
    const float* w_score = (const float*)d_in[5];
    const float* b_score = (const float*)d_in[6];

    float* out  = (float*)d_out;
    float* ctx  = out;                            // context: B*N*H
    float* pair = out + (size_t)BB * NN * HH;     // atom_pair: B*N*N*H

    proj_kernel<<<BB * NN / 16, 256>>>(x, W_atom);
    pair_kernel<<<BB * NN / IT, 256>>>(x, bin, W_bin, b_bin, w_score, b_score, ctx, pair);
}

// round 4
// speedup vs baseline: 1.5204x; 1.0769x over previous
#include <cuda_runtime.h>
#include <math.h>

#define BB   16
#define NN   96
#define HH   256
#define BINC 11
#define IT   4      // i-rows per block (pair kernel)

// Scratch for y = x @ W_atom  (1.5 MB) — __device__ global, no allocation.
__device__ float g_y[BB * NN * HH];

// ---- packed f32x2 helpers (u64 carrier, "l" constraints) ------------------
typedef unsigned long long f2;
__device__ __forceinline__ f2 pk(float lo, float hi) {
    f2 r; asm("mov.b64 %0, {%1,%2};" : "=l"(r) : "f"(lo), "f"(hi)); return r;
}
__device__ __forceinline__ void upk(f2 v, float& lo, float& hi) {
    asm("mov.b64 {%0,%1}, %2;" : "=f"(lo), "=f"(hi) : "l"(v));
}
__device__ __forceinline__ f2 fma2(f2 a, f2 b, f2 c) {
    f2 d; asm("fma.rn.f32x2 %0, %1, %2, %3;" : "=l"(d) : "l"(a), "l"(b), "l"(c)); return d;
}
__device__ __forceinline__ f2 add2(f2 a, f2 b) {
    f2 d; asm("add.rn.f32x2 %0, %1, %2;" : "=l"(d) : "l"(a), "l"(b)); return d;
}

// ---------------------------------------------------------------------------
// Kernel 1: y = x @ W_atom. 8 rows per block -> 192 blocks (fills the chip).
// ---------------------------------------------------------------------------
#define PR 8
__global__ __launch_bounds__(256) void proj_kernel(const float* __restrict__ x,
                                                   const float* __restrict__ W) {
    __shared__ float xs[PR * HH];
    const int r0  = blockIdx.x * PR;
    const int tid = threadIdx.x;
    for (int idx = tid; idx < PR * HH; idx += 256) xs[idx] = x[r0 * HH + idx];
    __syncthreads();

    const int k = tid;
    f2 acc[PR];
#pragma unroll
    for (int r = 0; r < PR; ++r) acc[r] = 0ull;

    const ulonglong2* xs2 = (const ulonglong2*)xs;   // [r*64 + h4]
#pragma unroll 4
    for (int h4 = 0; h4 < 64; ++h4) {
        const int h = h4 * 4;
        float w0 = __ldg(&W[(h + 0) * HH + k]);
        float w1 = __ldg(&W[(h + 1) * HH + k]);
        float w2 = __ldg(&W[(h + 2) * HH + k]);
        float w3 = __ldg(&W[(h + 3) * HH + k]);
        f2 wa = pk(w0, w1), wb = pk(w2, w3);
#pragma unroll
        for (int r = 0; r < PR; ++r) {
            ulonglong2 xv = xs2[r * 64 + h4];
            acc[r] = fma2(xv.x, wa, acc[r]);
            acc[r] = fma2(xv.y, wb, acc[r]);
        }
    }
#pragma unroll
    for (int r = 0; r < PR; ++r) {
        float lo, hi; upk(acc[r], lo, hi);
        g_y[(r0 + r) * HH + k] = lo + hi;
    }
}

// ---------------------------------------------------------------------------
// Kernel 2: pair + raw score in the hot loop; sigmoid + context deferred.
// Block = (b, 4 i's). Warp w: i = i0+(w&3), phase p = w>>2.
// Each iteration handles TWO j's (j0 = 4t+2p, j1 = j0+1): two independent
// hidden/score chains; both scores reduced together as one packed f32x2.
// ---------------------------------------------------------------------------
__global__ __launch_bounds__(256, 1) void pair_kernel(
    const float* __restrict__ x,
    const float* __restrict__ bin,
    const float* __restrict__ W_bin,
    const float* __restrict__ b_bin,
    const float* __restrict__ w_score,
    const float* __restrict__ b_score,
    float* __restrict__ ctx_out,
    float* __restrict__ pair_out)
{
    const int blk = blockIdx.x;
    const int b   = blk / (NN / IT);
    const int i0  = (blk % (NN / IT)) * IT;
    const int tid = threadIdx.x;
    const int w   = tid >> 5;
    const int L   = tid & 31;
    const int iw  = w & 3;
    const int p   = w >> 2;                 // j-phase 0/1
    const int bi  = b * NN + i0 + iw;

    __shared__ float att_s[IT][NN];         // raw scores, sigmoid later

    // ---- register-resident parameters (thread's k-slice: quads at 128t+4L) ----
    f2 wb[BINC][4];
#pragma unroll
    for (int c = 0; c < BINC; ++c) {
        const ulonglong2* pw = (const ulonglong2*)(W_bin + c * HH);
        ulonglong2 a = pw[L], bq = pw[32 + L];
        wb[c][0] = a.x; wb[c][1] = a.y; wb[c][2] = bq.x; wb[c][3] = bq.y;
    }
    f2 ws[4];
    {
        const ulonglong2* pw = (const ulonglong2*)w_score;
        ulonglong2 a = pw[L], bq = pw[32 + L];
        ws[0] = a.x; ws[1] = a.y; ws[2] = bq.x; ws[3] = bq.y;
    }
    f2 base[4], xi[4];
    {
        const ulonglong2* yp = (const ulonglong2*)(g_y + bi * HH);
        const ulonglong2* bp = (const ulonglong2*)b_bin;
        const ulonglong2* xp = (const ulonglong2*)(x + bi * HH);
        ulonglong2 y0 = yp[L], y1 = yp[32 + L];
        ulonglong2 b0 = bp[L], b1 = bp[32 + L];
        ulonglong2 x0 = xp[L], x1 = xp[32 + L];
        base[0] = add2(y0.x, b0.x); base[1] = add2(y0.y, b0.y);
        base[2] = add2(y1.x, b1.x); base[3] = add2(y1.y, b1.y);
        xi[0] = x0.x; xi[1] = x0.y; xi[2] = x1.x; xi[3] = x1.y;
    }

    const ulonglong2* ybase = (const ulonglong2*)(g_y + b * NN * HH);
    const ulonglong2* xbase = (const ulonglong2*)(x   + b * NN * HH);
    const float*      binb  = bin + (size_t)bi * NN * BINC;
    ulonglong2*       pob   = (ulonglong2*)(pair_out + (size_t)bi * NN * HH);

    // ---- preload first j-pair ----
    int jf0 = 2 * p, jf1 = jf0 + 1;
    ulonglong2 ya0 = ybase[jf0 * 64 + L], yb0 = ybase[jf0 * 64 + 32 + L];
    ulonglong2 xa0 = xbase[jf0 * 64 + L], xb0 = xbase[jf0 * 64 + 32 + L];
    ulonglong2 ya1 = ybase[jf1 * 64 + L], yb1 = ybase[jf1 * 64 + 32 + L];
    ulonglong2 xa1 = xbase[jf1 * 64 + L], xb1 = xbase[jf1 * 64 + 32 + L];
    float bc0[BINC], bc1[BINC];
#pragma unroll
    for (int c = 0; c < BINC; ++c) { bc0[c] = __ldg(binb + jf0 * BINC + c);
                                     bc1[c] = __ldg(binb + jf1 * BINC + c); }

    for (int t = 0; t < NN / 4; ++t) {
        const int j0 = 4 * t + 2 * p, j1 = j0 + 1;

        // consume buffers: hidden init + pair sums (both j's)
        f2 h00 = add2(base[0], ya0.x), h01 = add2(base[1], ya0.y);
        f2 h02 = add2(base[2], yb0.x), h03 = add2(base[3], yb0.y);
        f2 h10 = add2(base[0], ya1.x), h11 = add2(base[1], ya1.y);
        f2 h12 = add2(base[2], yb1.x), h13 = add2(base[3], yb1.y);
        f2 p00 = add2(xi[0], xa0.x),  p01 = add2(xi[1], xa0.y);
        f2 p02 = add2(xi[2], xb0.x),  p03 = add2(xi[3], xb0.y);
        f2 p10 = add2(xi[0], xa1.x),  p11 = add2(xi[1], xa1.y);
        f2 p12 = add2(xi[2], xb1.x),  p13 = add2(xi[3], xb1.y);

        // atom_pair stores (4x STG.128 per j)
        pob[j0 * 64 + L]      = make_ulonglong2(p00, p01);
        pob[j0 * 64 + 32 + L] = make_ulonglong2(p02, p03);
        pob[j1 * 64 + L]      = make_ulonglong2(p10, p11);
        pob[j1 * 64 + 32 + L] = make_ulonglong2(p12, p13);

        // prefetch next pair's y/x (buffers dead)
        const int tn  = (t < NN / 4 - 1) ? t + 1 : t;
        const int jn0 = 4 * tn + 2 * p, jn1 = jn0 + 1;
        ya0 = ybase[jn0 * 64 + L]; yb0 = ybase[jn0 * 64 + 32 + L];
        xa0 = xbase[jn0 * 64 + L]; xb0 = xbase[jn0 * 64 + 32 + L];
        ya1 = ybase[jn1 * 64 + L]; yb1 = ybase[jn1 * 64 + 32 + L];
        xa1 = xbase[jn1 * 64 + L]; xb1 = xbase[jn1 * 64 + 32 + L];

        // bin projections: two independent 11-FMA2x4 chains
#pragma unroll
        for (int c = 0; c < BINC; ++c) {
            f2 s0 = pk(bc0[c], bc0[c]);
            f2 s1 = pk(bc1[c], bc1[c]);
            h00 = fma2(s0, wb[c][0], h00); h10 = fma2(s1, wb[c][0], h10);
            h01 = fma2(s0, wb[c][1], h01); h11 = fma2(s1, wb[c][1], h11);
            h02 = fma2(s0, wb[c][2], h02); h12 = fma2(s1, wb[c][2], h12);
            h03 = fma2(s0, wb[c][3], h03); h13 = fma2(s1, wb[c][3], h13);
        }
        // prefetch next pair's bin coeffs
#pragma unroll
        for (int c = 0; c < BINC; ++c) { bc0[c] = __ldg(binb + jn0 * BINC + c);
                                         bc1[c] = __ldg(binb + jn1 * BINC + c); }

        // relu + score dot, both j's
        float a0, a1, a2, a3, a4, a5, a6, a7;
        upk(h00, a0, a1); upk(h01, a2, a3); upk(h02, a4, a5); upk(h03, a6, a7);
        a0 = fmaxf(a0, 0.f); a1 = fmaxf(a1, 0.f); a2 = fmaxf(a2, 0.f); a3 = fmaxf(a3, 0.f);
        a4 = fmaxf(a4, 0.f); a5 = fmaxf(a5, 0.f); a6 = fmaxf(a6, 0.f); a7 = fmaxf(a7, 0.f);
        f2 q0 = pk(a0, a1), q1 = pk(a2, a3), q2 = pk(a4, a5), q3 = pk(a6, a7);
        f2 d0 = fma2(q0, ws[0], fma2(q1, ws[1], fma2(q2, ws[2], fma2(q3, ws[3], 0ull))));

        upk(h10, a0, a1); upk(h11, a2, a3); upk(h12, a4, a5); upk(h13, a6, a7);
        a0 = fmaxf(a0, 0.f); a1 = fmaxf(a1, 0.f); a2 = fmaxf(a2, 0.f); a3 = fmaxf(a3, 0.f);
        a4 = fmaxf(a4, 0.f); a5 = fmaxf(a5, 0.f); a6 = fmaxf(a6, 0.f); a7 = fmaxf(a7, 0.f);
        q0 = pk(a0, a1); q1 = pk(a2, a3); q2 = pk(a4, a5); q3 = pk(a6, a7);
        f2 d1 = fma2(q0, ws[0], fma2(q1, ws[1], fma2(q2, ws[2], fma2(q3, ws[3], 0ull))));

        float s0l, s0h, s1l, s1h;
        upk(d0, s0l, s0h); upk(d1, s1l, s1h);
        // packed score pair: lo = score(j0) partial, hi = score(j1) partial
        f2 sp = pk(s0l + s0h, s1l + s1h);
#pragma unroll
        for (int off = 16; off > 0; off >>= 1)
            sp = add2(sp, __shfl_xor_sync(0xffffffffu, sp, off));

        if (L == 0) {
            float r0, r1; upk(sp, r0, r1);
            att_s[iw][j0] = r0;
            att_s[iw][j1] = r1;
        }
    }
    __syncthreads();

    // ---- sigmoid pass ----
    const float bsc = __ldg(b_score);
    for (int idx = tid; idx < IT * NN; idx += 256) {
        float v = (&att_s[0][0])[idx];
        (&att_s[0][0])[idx] = 1.f / (1.f + __expf(-(v + bsc)));
    }
    __syncthreads();

    // ---- context epilogue: ctx[i,k] = sum_j att[i][j] * x[b,j,k] ----
    const float* xrow = x + (size_t)b * NN * HH + tid;   // thread owns k = tid
    float c0 = 0.f, c1 = 0.f, c2 = 0.f, c3 = 0.f;
#pragma unroll 4
    for (int jj = 0; jj < NN; ++jj) {
        const float xv = xrow[jj * HH];
        c0 = fmaf(att_s[0][jj], xv, c0);
        c1 = fmaf(att_s[1][jj], xv, c1);
        c2 = fmaf(att_s[2][jj], xv, c2);
        c3 = fmaf(att_s[3][jj], xv, c3);
    }
    float* co = ctx_out + (size_t)(b * NN + i0) * HH + tid;
    co[0 * HH] = c0; co[1 * HH] = c1; co[2 * HH] = c2; co[3 * HH] = c3;
}

// ---------------------------------------------------------------------------
extern "C" void kernel_launch(void* const* d_in, const int* in_sizes, int n_in,
                              void* d_out, int out_size) {
    const float* x       = (const float*)d_in[0];
    const float* bin     = (const float*)d_in[1];
    const float* W_atom  = (const float*)d_in[2];
    const float* W_bin   = (const float*)d_in[3];
    const float* b_bin   = (const float*)d_in[4];
    const float* w_score = (const float*)d_in[5];
    const float* b_score = (const float*)d_in[6];

    float* out  = (float*)d_out;
    float* ctx  = out;                            // context: B*N*H
    float* pair = out + (size_t)BB * NN * HH;     // atom_pair: B*N*N*H

    proj_kernel<<<BB * NN / PR, 256>>>(x, W_atom);
    pair_kernel<<<BB * NN / IT, 256>>>(x, bin, W_bin, b_bin, w_score, b_score, ctx, pair);
}